// round 4
// baseline (speedup 1.0000x reference)
#include <cuda_runtime.h>
#include <cuda_bf16.h>
#include <math.h>

#define NN 50000
#define NE 800000

// ---------------- device scratch (no allocation allowed) ----------------
__device__ float g_xl1[NN * 128];
__device__ float g_xr1[NN * 128];
__device__ float g_h1 [NN * 128];
__device__ float g_xl2[NN * 64];
__device__ float g_xr2[NN * 64];
__device__ int   g_cnt[NN];          // histogram, then scatter cursor
__device__ int   g_rowptr[NN + 1];
__device__ int   g_blocksum[64];
__device__ int   g_src[NE];
__device__ float g_ea [NE];

// ---------------- CSR build ----------------
__global__ void k_zero() {
    int i = blockIdx.x * blockDim.x + threadIdx.x;
    for (; i < NN; i += gridDim.x * blockDim.x) g_cnt[i] = 0;
}

// edge_index is int32: [2, NE] row-major. ei[e] = src, ei[NE+e] = dst.
__global__ void k_hist(const int* __restrict__ ei) {
    int e = blockIdx.x * blockDim.x + threadIdx.x;
    if (e < NE) {
        unsigned dst = (unsigned)ei[NE + e];
        if (dst < NN) atomicAdd(&g_cnt[dst], 1);
    }
}

__global__ void k_scan1() {
    __shared__ int sh[1024];
    int i = blockIdx.x * 1024 + threadIdx.x;
    int v = (i < NN) ? g_cnt[i] : 0;
    sh[threadIdx.x] = v;
    __syncthreads();
    for (int off = 1; off < 1024; off <<= 1) {
        int t = (threadIdx.x >= off) ? sh[threadIdx.x - off] : 0;
        __syncthreads();
        sh[threadIdx.x] += t;
        __syncthreads();
    }
    int incl = sh[threadIdx.x];
    if (i < NN) g_rowptr[i] = incl - v;   // block-local exclusive
    if (threadIdx.x == 1023) g_blocksum[blockIdx.x] = incl;
}

__global__ void k_scan2(int nblk) {
    if (threadIdx.x == 0 && blockIdx.x == 0) {
        int run = 0;
        for (int i = 0; i < nblk; i++) {
            int v = g_blocksum[i];
            g_blocksum[i] = run;
            run += v;
        }
    }
}

__global__ void k_scan3() {
    int i = blockIdx.x * blockDim.x + threadIdx.x;
    if (i < NN) {
        int r = g_rowptr[i] + g_blocksum[i >> 10];
        g_rowptr[i] = r;
        g_cnt[i] = r;       // cursor for scatter
    }
    if (i == 0) g_rowptr[NN] = NE;
}

__global__ void k_scatter(const int* __restrict__ ei,
                          const float* __restrict__ edge_attr) {
    int e = blockIdx.x * blockDim.x + threadIdx.x;
    if (e < NE) {
        unsigned dst = (unsigned)ei[NE + e];
        unsigned src = (unsigned)ei[e];
        if (dst < NN && src < NN) {
            int pos = atomicAdd(&g_cnt[dst], 1);
            g_src[pos] = (int)src;
            g_ea[pos]  = edge_attr[e];
        }
    }
}

// ---------------- Layer 1 projections: x[N,10] @ W[10,128] ----------------
__global__ __launch_bounds__(128) void k_proj1(const float* __restrict__ x,
                                               const float* __restrict__ Wl,
                                               const float* __restrict__ Wr) {
    __shared__ float swl[10 * 128];
    __shared__ float swr[10 * 128];
    int c = threadIdx.x;
    for (int k = c; k < 10 * 128; k += 128) { swl[k] = Wl[k]; swr[k] = Wr[k]; }
    __syncthreads();
    int n0 = blockIdx.x * 8;
#pragma unroll
    for (int t = 0; t < 8; t++) {
        int n = n0 + t;
        if (n >= NN) break;
        float al = 0.f, ar = 0.f;
#pragma unroll
        for (int k = 0; k < 10; k++) {
            float xv = x[n * 10 + k];
            al = fmaf(xv, swl[k * 128 + c], al);
            ar = fmaf(xv, swr[k * 128 + c], ar);
        }
        g_xl1[n * 128 + c] = al;
        g_xr1[n * 128 + c] = ar;
    }
}

// ---------------- Layer 1: fused edge-softmax aggregation + bias + LN + ELU ----------------
// one warp per dst node; lane owns channels {lane, 32+lane, 64+lane, 96+lane} (one per head)
__global__ __launch_bounds__(256) void k_agg1(const float* __restrict__ att1,
                                              const float* __restrict__ W1e,
                                              const float* __restrict__ b1,
                                              const float* __restrict__ g1,
                                              const float* __restrict__ be1) {
    int warp = threadIdx.x >> 5, lane = threadIdx.x & 31;
    int node = blockIdx.x * 8 + warp;
    if (node >= NN) return;

    float att[4], we[4], xli[4], acc[4], den[4];
#pragma unroll
    for (int j = 0; j < 4; j++) {
        int c = j * 32 + lane;
        att[j] = att1[c];
        we[j]  = W1e[c];
        xli[j] = g_xl1[node * 128 + c];
        acc[j] = 0.f;
        den[j] = 0.f;
    }

    int p0 = g_rowptr[node], p1 = g_rowptr[node + 1];
    for (int p = p0; p < p1; p++) {
        int   s  = g_src[p];
        float ea = g_ea[p];
        float xr[4], lg[4];
#pragma unroll
        for (int j = 0; j < 4; j++) {
            xr[j] = g_xr1[s * 128 + j * 32 + lane];
            float t = fmaf(ea, we[j], xli[j] + xr[j]);
            t = fmaxf(t, 0.2f * t);          // leaky_relu(0.2)
            lg[j] = t * att[j];
        }
#pragma unroll
        for (int off = 16; off; off >>= 1) {
#pragma unroll
            for (int j = 0; j < 4; j++)
                lg[j] += __shfl_xor_sync(0xffffffffu, lg[j], off);
        }
#pragma unroll
        for (int j = 0; j < 4; j++) {
            float w = __expf(lg[j]);         // softmax without max-shift (logits O(1))
            den[j] += w;
            acc[j] = fmaf(w, xr[j], acc[j]);
        }
    }

    float o[4];
#pragma unroll
    for (int j = 0; j < 4; j++) {
        float v = (den[j] > 0.f) ? acc[j] / den[j] : 0.f;
        o[j] = v + b1[j * 32 + lane];
    }
    // LayerNorm over 128
    float s = o[0] + o[1] + o[2] + o[3];
#pragma unroll
    for (int off = 16; off; off >>= 1) s += __shfl_xor_sync(0xffffffffu, s, off);
    float mu = s * (1.f / 128.f);
    float vs = 0.f;
#pragma unroll
    for (int j = 0; j < 4; j++) { float d = o[j] - mu; vs = fmaf(d, d, vs); }
#pragma unroll
    for (int off = 16; off; off >>= 1) vs += __shfl_xor_sync(0xffffffffu, vs, off);
    float rstd = rsqrtf(vs * (1.f / 128.f) + 1e-5f);
#pragma unroll
    for (int j = 0; j < 4; j++) {
        int c = j * 32 + lane;
        float y = (o[j] - mu) * rstd * g1[c] + be1[c];
        y = (y > 0.f) ? y : expm1f(y);       // ELU
        g_h1[node * 128 + c] = y;
    }
}

// ---------------- Layer 2 projections: h1[N,128] @ W[128,64] ----------------
// which = 0 -> g_xl2, which = 1 -> g_xr2
__global__ __launch_bounds__(256) void k_proj2(const float* __restrict__ W, int which) {
    __shared__ float sw[128 * 64];    // [k][oc]
    __shared__ float shh[32 * 128];   // [node][k]
    int tid = threadIdx.x;
    int oc = tid & 63, part = tid >> 6;   // 64 oc x 4 parts
    for (int idx = tid; idx < 128 * 64; idx += 256) sw[idx] = W[idx];
    int n0 = blockIdx.x * 32;
    for (int idx = tid; idx < 32 * 128; idx += 256) {
        int n = n0 + (idx >> 7);
        shh[idx] = (n < NN) ? g_h1[n * 128 + (idx & 127)] : 0.f;
    }
    __syncthreads();

    float accv[8];
#pragma unroll
    for (int i = 0; i < 8; i++) accv[i] = 0.f;

#pragma unroll 4
    for (int k = 0; k < 128; k += 4) {
        float w0 = sw[(k + 0) * 64 + oc];
        float w1 = sw[(k + 1) * 64 + oc];
        float w2 = sw[(k + 2) * 64 + oc];
        float w3 = sw[(k + 3) * 64 + oc];
#pragma unroll
        for (int i = 0; i < 8; i++) {
            int nn = part + i * 4;                 // rows part, part+4, ..., part+28
            float4 h4 = *(const float4*)&shh[nn * 128 + k];
            accv[i] = fmaf(h4.x, w0, fmaf(h4.y, w1, fmaf(h4.z, w2, fmaf(h4.w, w3, accv[i]))));
        }
    }
    float* outp = which ? g_xr2 : g_xl2;
#pragma unroll
    for (int i = 0; i < 8; i++) {
        int n = n0 + part + i * 4;
        if (n < NN) outp[n * 64 + oc] = accv[i];
    }
}

// ---------------- Layer 2: fused edge-softmax aggregation + bias + LN + ELU -> out ----------------
__global__ __launch_bounds__(256) void k_agg2(const float* __restrict__ att2,
                                              const float* __restrict__ W2e,
                                              const float* __restrict__ b2,
                                              const float* __restrict__ g2,
                                              const float* __restrict__ be2,
                                              float* __restrict__ out) {
    int warp = threadIdx.x >> 5, lane = threadIdx.x & 31;
    int node = blockIdx.x * 8 + warp;
    if (node >= NN) return;

    float a0 = att2[lane],  a1 = att2[32 + lane];
    float w0 = W2e[lane],   w1 = W2e[32 + lane];
    float xi0 = g_xl2[node * 64 + lane];
    float xi1 = g_xl2[node * 64 + 32 + lane];
    float acc0 = 0.f, acc1 = 0.f, den = 0.f;

    int p0 = g_rowptr[node], p1 = g_rowptr[node + 1];
    for (int p = p0; p < p1; p++) {
        int   s  = g_src[p];
        float ea = g_ea[p];
        float xr0 = g_xr2[s * 64 + lane];
        float xr1 = g_xr2[s * 64 + 32 + lane];
        float t0 = fmaf(ea, w0, xi0 + xr0); t0 = fmaxf(t0, 0.2f * t0);
        float t1 = fmaf(ea, w1, xi1 + xr1); t1 = fmaxf(t1, 0.2f * t1);
        float lg = fmaf(t0, a0, t1 * a1);
#pragma unroll
        for (int off = 16; off; off >>= 1)
            lg += __shfl_xor_sync(0xffffffffu, lg, off);
        float w = __expf(lg);
        den += w;
        acc0 = fmaf(w, xr0, acc0);
        acc1 = fmaf(w, xr1, acc1);
    }

    float o0 = ((den > 0.f) ? acc0 / den : 0.f) + b2[lane];
    float o1 = ((den > 0.f) ? acc1 / den : 0.f) + b2[32 + lane];
    // LayerNorm over 64
    float s = o0 + o1;
#pragma unroll
    for (int off = 16; off; off >>= 1) s += __shfl_xor_sync(0xffffffffu, s, off);
    float mu = s * (1.f / 64.f);
    float d0 = o0 - mu, d1 = o1 - mu;
    float vs = fmaf(d0, d0, d1 * d1);
#pragma unroll
    for (int off = 16; off; off >>= 1) vs += __shfl_xor_sync(0xffffffffu, vs, off);
    float rstd = rsqrtf(vs * (1.f / 64.f) + 1e-5f);
    float y0 = d0 * rstd * g2[lane]      + be2[lane];
    float y1 = d1 * rstd * g2[32 + lane] + be2[32 + lane];
    y0 = (y0 > 0.f) ? y0 : expm1f(y0);
    y1 = (y1 > 0.f) ? y1 : expm1f(y1);
    out[node * 64 + lane]      = y0;
    out[node * 64 + 32 + lane] = y1;
}

// ---------------- launcher ----------------
extern "C" void kernel_launch(void* const* d_in, const int* in_sizes, int n_in,
                              void* d_out, int out_size) {
    const float* x    = (const float*)d_in[0];
    const float* ea   = (const float*)d_in[1];
    const float* W1l  = (const float*)d_in[2];
    const float* W1r  = (const float*)d_in[3];
    const float* W1e  = (const float*)d_in[4];
    const float* att1 = (const float*)d_in[5];
    const float* b1   = (const float*)d_in[6];
    const float* ln1g = (const float*)d_in[7];
    const float* ln1b = (const float*)d_in[8];
    const float* W2l  = (const float*)d_in[9];
    const float* W2r  = (const float*)d_in[10];
    const float* W2e  = (const float*)d_in[11];
    const float* att2 = (const float*)d_in[12];
    const float* b2   = (const float*)d_in[13];
    const float* ln2g = (const float*)d_in[14];
    const float* ln2b = (const float*)d_in[15];
    const int*   ei   = (const int*)d_in[16];   // int32 [2, NE]
    float* out = (float*)d_out;

    const int NBLK_SCAN = (NN + 1023) / 1024;   // 49

    k_zero<<<200, 256>>>();
    k_hist<<<(NE + 255) / 256, 256>>>(ei);
    k_scan1<<<NBLK_SCAN, 1024>>>();
    k_scan2<<<1, 32>>>(NBLK_SCAN);
    k_scan3<<<(NN + 255) / 256, 256>>>();
    k_scatter<<<(NE + 255) / 256, 256>>>(ei, ea);

    k_proj1<<<(NN + 7) / 8, 128>>>(x, W1l, W1r);
    k_agg1<<<(NN + 7) / 8, 256>>>(att1, W1e, b1, ln1g, ln1b);

    k_proj2<<<(NN + 31) / 32, 256>>>(W2l, 0);
    k_proj2<<<(NN + 31) / 32, 256>>>(W2r, 1);
    k_agg2<<<(NN + 7) / 8, 256>>>(att2, W2e, b2, ln2g, ln2b, out);
}

// round 5
// speedup vs baseline: 1.4264x; 1.4264x over previous
#include <cuda_runtime.h>
#include <cuda_bf16.h>
#include <math.h>

#define NN 50000
#define NE 800000

// ---------------- device scratch ----------------
__device__ float g_xl1[NN * 128];
__device__ float g_xr1[NN * 128];
__device__ float g_h1 [NN * 128];
__device__ float g_xl2[NN * 64];
__device__ float g_xr2[NN * 64];
__device__ int   g_cnt[NN];
__device__ int   g_rowptr[NN + 1];
__device__ int   g_blocksum[64];
__device__ int   g_src[NE];
__device__ float g_ea [NE];

// ---------------- CSR build ----------------
__global__ void k_zero() {
    int i = blockIdx.x * blockDim.x + threadIdx.x;
    for (; i < NN; i += gridDim.x * blockDim.x) g_cnt[i] = 0;
}

__global__ void k_hist(const int* __restrict__ ei) {
    int e = blockIdx.x * blockDim.x + threadIdx.x;
    if (e < NE) {
        unsigned dst = (unsigned)ei[NE + e];
        if (dst < NN) atomicAdd(&g_cnt[dst], 1);
    }
}

__global__ void k_scan1() {
    __shared__ int sh[1024];
    int i = blockIdx.x * 1024 + threadIdx.x;
    int v = (i < NN) ? g_cnt[i] : 0;
    sh[threadIdx.x] = v;
    __syncthreads();
    for (int off = 1; off < 1024; off <<= 1) {
        int t = (threadIdx.x >= off) ? sh[threadIdx.x - off] : 0;
        __syncthreads();
        sh[threadIdx.x] += t;
        __syncthreads();
    }
    int incl = sh[threadIdx.x];
    if (i < NN) g_rowptr[i] = incl - v;
    if (threadIdx.x == 1023) g_blocksum[blockIdx.x] = incl;
}

// parallel exclusive scan of up to 64 block sums (was 1-thread serial: 4.9us)
__global__ void k_scan2(int nblk) {
    __shared__ int sh[64];
    int t = threadIdx.x;
    int v = (t < nblk) ? g_blocksum[t] : 0;
    sh[t] = v;
    __syncthreads();
    for (int off = 1; off < 64; off <<= 1) {
        int u = (t >= off) ? sh[t - off] : 0;
        __syncthreads();
        sh[t] += u;
        __syncthreads();
    }
    if (t < nblk) g_blocksum[t] = sh[t] - v;   // exclusive
}

__global__ void k_scan3() {
    int i = blockIdx.x * blockDim.x + threadIdx.x;
    if (i < NN) {
        int r = g_rowptr[i] + g_blocksum[i >> 10];
        g_rowptr[i] = r;
        g_cnt[i] = r;
    }
    if (i == 0) g_rowptr[NN] = NE;
}

__global__ void k_scatter(const int* __restrict__ ei,
                          const float* __restrict__ edge_attr) {
    int e = blockIdx.x * blockDim.x + threadIdx.x;
    if (e < NE) {
        unsigned dst = (unsigned)ei[NE + e];
        unsigned src = (unsigned)ei[e];
        if (dst < NN && src < NN) {
            int pos = atomicAdd(&g_cnt[dst], 1);
            g_src[pos] = (int)src;
            g_ea[pos]  = edge_attr[e];
        }
    }
}

// ---------------- Layer 1 projections: x[N,10] @ W[10,128] ----------------
__global__ __launch_bounds__(128) void k_proj1(const float* __restrict__ x,
                                               const float* __restrict__ Wl,
                                               const float* __restrict__ Wr) {
    __shared__ float swl[10 * 128];
    __shared__ float swr[10 * 128];
    int c = threadIdx.x;
    for (int k = c; k < 10 * 128; k += 128) { swl[k] = Wl[k]; swr[k] = Wr[k]; }
    __syncthreads();
    int n0 = blockIdx.x * 8;
#pragma unroll
    for (int t = 0; t < 8; t++) {
        int n = n0 + t;
        if (n >= NN) break;
        float al = 0.f, ar = 0.f;
#pragma unroll
        for (int k = 0; k < 10; k++) {
            float xv = x[n * 10 + k];
            al = fmaf(xv, swl[k * 128 + c], al);
            ar = fmaf(xv, swr[k * 128 + c], ar);
        }
        g_xl1[n * 128 + c] = al;
        g_xr1[n * 128 + c] = ar;
    }
}

// ---------------- Layer 1 agg: head = lane>>3, lane owns 4 consecutive channels ----------
// Logit reduce = 3 lane-local adds + 3 shfls within the 8-lane head group.
// xr gather is one float4 per lane (warp reads 512B contiguous).
__global__ __launch_bounds__(256) void k_agg1(const float* __restrict__ att1,
                                              const float* __restrict__ W1e,
                                              const float* __restrict__ b1,
                                              const float* __restrict__ g1,
                                              const float* __restrict__ be1) {
    int warp = threadIdx.x >> 5, lane = threadIdx.x & 31;
    int node = blockIdx.x * 8 + warp;
    if (node >= NN) return;

    int cb = (lane >> 3) * 32 + (lane & 7) * 4;   // base channel (multiple of 4)

    float4 att = *(const float4*)(att1 + cb);
    float4 we  = *(const float4*)(W1e  + cb);
    float4 xli = *(const float4*)(g_xl1 + node * 128 + cb);
    float4 acc = make_float4(0.f, 0.f, 0.f, 0.f);
    float  den = 0.f;

    const float4* xr_base = (const float4*)g_xr1;   // [node][32 float4s]
    int fidx = cb >> 2;

    int p0 = g_rowptr[node], p1 = g_rowptr[node + 1];
    int p = p0;
    for (; p + 1 < p1; p += 2) {
        int   s0  = g_src[p],     s1  = g_src[p + 1];
        float ea0 = g_ea[p],      ea1 = g_ea[p + 1];
        float4 xr0 = xr_base[s0 * 32 + fidx];
        float4 xr1 = xr_base[s1 * 32 + fidx];

        float t, lg0, lg1;
        t = fmaf(ea0, we.x, xli.x + xr0.x); t = fmaxf(t, 0.2f * t); lg0 = t * att.x;
        t = fmaf(ea0, we.y, xli.y + xr0.y); t = fmaxf(t, 0.2f * t); lg0 = fmaf(t, att.y, lg0);
        t = fmaf(ea0, we.z, xli.z + xr0.z); t = fmaxf(t, 0.2f * t); lg0 = fmaf(t, att.z, lg0);
        t = fmaf(ea0, we.w, xli.w + xr0.w); t = fmaxf(t, 0.2f * t); lg0 = fmaf(t, att.w, lg0);
        t = fmaf(ea1, we.x, xli.x + xr1.x); t = fmaxf(t, 0.2f * t); lg1 = t * att.x;
        t = fmaf(ea1, we.y, xli.y + xr1.y); t = fmaxf(t, 0.2f * t); lg1 = fmaf(t, att.y, lg1);
        t = fmaf(ea1, we.z, xli.z + xr1.z); t = fmaxf(t, 0.2f * t); lg1 = fmaf(t, att.z, lg1);
        t = fmaf(ea1, we.w, xli.w + xr1.w); t = fmaxf(t, 0.2f * t); lg1 = fmaf(t, att.w, lg1);

#pragma unroll
        for (int off = 4; off; off >>= 1) {
            lg0 += __shfl_xor_sync(0xffffffffu, lg0, off);
            lg1 += __shfl_xor_sync(0xffffffffu, lg1, off);
        }
        float w0 = __expf(lg0);
        float w1 = __expf(lg1);
        den += w0 + w1;
        acc.x = fmaf(w0, xr0.x, fmaf(w1, xr1.x, acc.x));
        acc.y = fmaf(w0, xr0.y, fmaf(w1, xr1.y, acc.y));
        acc.z = fmaf(w0, xr0.z, fmaf(w1, xr1.z, acc.z));
        acc.w = fmaf(w0, xr0.w, fmaf(w1, xr1.w, acc.w));
    }
    if (p < p1) {
        int   s0  = g_src[p];
        float ea0 = g_ea[p];
        float4 xr0 = xr_base[s0 * 32 + fidx];
        float t, lg0;
        t = fmaf(ea0, we.x, xli.x + xr0.x); t = fmaxf(t, 0.2f * t); lg0 = t * att.x;
        t = fmaf(ea0, we.y, xli.y + xr0.y); t = fmaxf(t, 0.2f * t); lg0 = fmaf(t, att.y, lg0);
        t = fmaf(ea0, we.z, xli.z + xr0.z); t = fmaxf(t, 0.2f * t); lg0 = fmaf(t, att.z, lg0);
        t = fmaf(ea0, we.w, xli.w + xr0.w); t = fmaxf(t, 0.2f * t); lg0 = fmaf(t, att.w, lg0);
#pragma unroll
        for (int off = 4; off; off >>= 1)
            lg0 += __shfl_xor_sync(0xffffffffu, lg0, off);
        float w0 = __expf(lg0);
        den += w0;
        acc.x = fmaf(w0, xr0.x, acc.x);
        acc.y = fmaf(w0, xr0.y, acc.y);
        acc.z = fmaf(w0, xr0.z, acc.z);
        acc.w = fmaf(w0, xr0.w, acc.w);
    }

    float inv = (den > 0.f) ? (1.f / den) : 0.f;
    float4 bb = *(const float4*)(b1 + cb);
    float o0 = acc.x * inv + bb.x;
    float o1 = acc.y * inv + bb.y;
    float o2 = acc.z * inv + bb.z;
    float o3 = acc.w * inv + bb.w;

    // LayerNorm over 128 (full-warp reduce)
    float s = o0 + o1 + o2 + o3;
#pragma unroll
    for (int off = 16; off; off >>= 1) s += __shfl_xor_sync(0xffffffffu, s, off);
    float mu = s * (1.f / 128.f);
    float d0 = o0 - mu, d1 = o1 - mu, d2 = o2 - mu, d3 = o3 - mu;
    float vs = fmaf(d0, d0, fmaf(d1, d1, fmaf(d2, d2, d3 * d3)));
#pragma unroll
    for (int off = 16; off; off >>= 1) vs += __shfl_xor_sync(0xffffffffu, vs, off);
    float rstd = rsqrtf(vs * (1.f / 128.f) + 1e-5f);

    float4 gg = *(const float4*)(g1  + cb);
    float4 be = *(const float4*)(be1 + cb);
    float y0 = d0 * rstd * gg.x + be.x; y0 = (y0 > 0.f) ? y0 : expm1f(y0);
    float y1 = d1 * rstd * gg.y + be.y; y1 = (y1 > 0.f) ? y1 : expm1f(y1);
    float y2 = d2 * rstd * gg.z + be.z; y2 = (y2 > 0.f) ? y2 : expm1f(y2);
    float y3 = d3 * rstd * gg.w + be.w; y3 = (y3 > 0.f) ? y3 : expm1f(y3);
    *(float4*)(g_h1 + node * 128 + cb) = make_float4(y0, y1, y2, y3);
}

// ---------------- Layer 2 dual projection: h1[N,128] @ {W2l,W2r}[128,64] ----------------
// shh tile loaded once, reused for both weight matrices; W loaded in two 64-k halves
// so static smem = 16KB (shh) + 2*16KB (W halves) = 48KB.
__global__ __launch_bounds__(256) void k_proj2(const float* __restrict__ Wl,
                                               const float* __restrict__ Wr) {
    __shared__ float shh[32 * 128];
    __shared__ float swl[64 * 64];
    __shared__ float swr[64 * 64];
    int tid = threadIdx.x;
    int oc = tid & 63, part = tid >> 6;
    int n0 = blockIdx.x * 32;
    for (int idx = tid; idx < 32 * 128; idx += 256) {
        int n = n0 + (idx >> 7);
        shh[idx] = (n < NN) ? g_h1[n * 128 + (idx & 127)] : 0.f;
    }

    float accl[8], accr[8];
#pragma unroll
    for (int i = 0; i < 8; i++) { accl[i] = 0.f; accr[i] = 0.f; }

#pragma unroll
    for (int half = 0; half < 2; half++) {
        __syncthreads();
        for (int idx = tid; idx < 64 * 64; idx += 256) {
            swl[idx] = Wl[half * 4096 + idx];
            swr[idx] = Wr[half * 4096 + idx];
        }
        __syncthreads();
        int kb = half * 64;
#pragma unroll 4
        for (int k = 0; k < 64; k += 4) {
            float l0 = swl[(k + 0) * 64 + oc], r0 = swr[(k + 0) * 64 + oc];
            float l1 = swl[(k + 1) * 64 + oc], r1 = swr[(k + 1) * 64 + oc];
            float l2 = swl[(k + 2) * 64 + oc], r2 = swr[(k + 2) * 64 + oc];
            float l3 = swl[(k + 3) * 64 + oc], r3 = swr[(k + 3) * 64 + oc];
#pragma unroll
            for (int i = 0; i < 8; i++) {
                int nn = part + i * 4;
                float4 h4 = *(const float4*)&shh[nn * 128 + kb + k];
                accl[i] = fmaf(h4.x, l0, fmaf(h4.y, l1, fmaf(h4.z, l2, fmaf(h4.w, l3, accl[i]))));
                accr[i] = fmaf(h4.x, r0, fmaf(h4.y, r1, fmaf(h4.z, r2, fmaf(h4.w, r3, accr[i]))));
            }
        }
    }
#pragma unroll
    for (int i = 0; i < 8; i++) {
        int n = n0 + part + i * 4;
        if (n < NN) {
            g_xl2[n * 64 + oc] = accl[i];
            g_xr2[n * 64 + oc] = accr[i];
        }
    }
}

// ---------------- Layer 2 agg: lane owns channels {2*lane, 2*lane+1} (float2) ----------
__global__ __launch_bounds__(256) void k_agg2(const float* __restrict__ att2,
                                              const float* __restrict__ W2e,
                                              const float* __restrict__ b2,
                                              const float* __restrict__ g2,
                                              const float* __restrict__ be2,
                                              float* __restrict__ out) {
    int warp = threadIdx.x >> 5, lane = threadIdx.x & 31;
    int node = blockIdx.x * 8 + warp;
    if (node >= NN) return;

    int cb = lane * 2;
    float2 att = *(const float2*)(att2 + cb);
    float2 we  = *(const float2*)(W2e  + cb);
    float2 xli = *(const float2*)(g_xl2 + node * 64 + cb);
    float acc0 = 0.f, acc1 = 0.f, den = 0.f;
    const float2* xr_base = (const float2*)g_xr2;   // [node][32 float2s]

    int p0 = g_rowptr[node], p1 = g_rowptr[node + 1];
    int p = p0;
    for (; p + 1 < p1; p += 2) {
        int   s0  = g_src[p],  s1  = g_src[p + 1];
        float ea0 = g_ea[p],   ea1 = g_ea[p + 1];
        float2 xr0 = xr_base[s0 * 32 + lane];
        float2 xr1 = xr_base[s1 * 32 + lane];

        float t, lgA, lgB;
        t = fmaf(ea0, we.x, xli.x + xr0.x); t = fmaxf(t, 0.2f * t); lgA = t * att.x;
        t = fmaf(ea0, we.y, xli.y + xr0.y); t = fmaxf(t, 0.2f * t); lgA = fmaf(t, att.y, lgA);
        t = fmaf(ea1, we.x, xli.x + xr1.x); t = fmaxf(t, 0.2f * t); lgB = t * att.x;
        t = fmaf(ea1, we.y, xli.y + xr1.y); t = fmaxf(t, 0.2f * t); lgB = fmaf(t, att.y, lgB);
#pragma unroll
        for (int off = 16; off; off >>= 1) {
            lgA += __shfl_xor_sync(0xffffffffu, lgA, off);
            lgB += __shfl_xor_sync(0xffffffffu, lgB, off);
        }
        float w0 = __expf(lgA);
        float w1 = __expf(lgB);
        den += w0 + w1;
        acc0 = fmaf(w0, xr0.x, fmaf(w1, xr1.x, acc0));
        acc1 = fmaf(w0, xr0.y, fmaf(w1, xr1.y, acc1));
    }
    if (p < p1) {
        int   s0  = g_src[p];
        float ea0 = g_ea[p];
        float2 xr0 = xr_base[s0 * 32 + lane];
        float t, lgA;
        t = fmaf(ea0, we.x, xli.x + xr0.x); t = fmaxf(t, 0.2f * t); lgA = t * att.x;
        t = fmaf(ea0, we.y, xli.y + xr0.y); t = fmaxf(t, 0.2f * t); lgA = fmaf(t, att.y, lgA);
#pragma unroll
        for (int off = 16; off; off >>= 1)
            lgA += __shfl_xor_sync(0xffffffffu, lgA, off);
        float w0 = __expf(lgA);
        den += w0;
        acc0 = fmaf(w0, xr0.x, acc0);
        acc1 = fmaf(w0, xr0.y, acc1);
    }

    float inv = (den > 0.f) ? (1.f / den) : 0.f;
    float2 bb = *(const float2*)(b2 + cb);
    float o0 = acc0 * inv + bb.x;
    float o1 = acc1 * inv + bb.y;

    float s = o0 + o1;
#pragma unroll
    for (int off = 16; off; off >>= 1) s += __shfl_xor_sync(0xffffffffu, s, off);
    float mu = s * (1.f / 64.f);
    float d0 = o0 - mu, d1 = o1 - mu;
    float vs = fmaf(d0, d0, d1 * d1);
#pragma unroll
    for (int off = 16; off; off >>= 1) vs += __shfl_xor_sync(0xffffffffu, vs, off);
    float rstd = rsqrtf(vs * (1.f / 64.f) + 1e-5f);

    float2 gg = *(const float2*)(g2  + cb);
    float2 be = *(const float2*)(be2 + cb);
    float y0 = d0 * rstd * gg.x + be.x; y0 = (y0 > 0.f) ? y0 : expm1f(y0);
    float y1 = d1 * rstd * gg.y + be.y; y1 = (y1 > 0.f) ? y1 : expm1f(y1);
    *(float2*)(out + node * 64 + cb) = make_float2(y0, y1);
}

// ---------------- launcher ----------------
extern "C" void kernel_launch(void* const* d_in, const int* in_sizes, int n_in,
                              void* d_out, int out_size) {
    const float* x    = (const float*)d_in[0];
    const float* ea   = (const float*)d_in[1];
    const float* W1l  = (const float*)d_in[2];
    const float* W1r  = (const float*)d_in[3];
    const float* W1e  = (const float*)d_in[4];
    const float* att1 = (const float*)d_in[5];
    const float* b1   = (const float*)d_in[6];
    const float* ln1g = (const float*)d_in[7];
    const float* ln1b = (const float*)d_in[8];
    const float* W2l  = (const float*)d_in[9];
    const float* W2r  = (const float*)d_in[10];
    const float* W2e  = (const float*)d_in[11];
    const float* att2 = (const float*)d_in[12];
    const float* b2   = (const float*)d_in[13];
    const float* ln2g = (const float*)d_in[14];
    const float* ln2b = (const float*)d_in[15];
    const int*   ei   = (const int*)d_in[16];   // int32 [2, NE]
    float* out = (float*)d_out;

    const int NBLK_SCAN = (NN + 1023) / 1024;   // 49

    k_zero<<<200, 256>>>();
    k_hist<<<(NE + 255) / 256, 256>>>(ei);
    k_scan1<<<NBLK_SCAN, 1024>>>();
    k_scan2<<<1, 64>>>(NBLK_SCAN);
    k_scan3<<<(NN + 255) / 256, 256>>>();
    k_scatter<<<(NE + 255) / 256, 256>>>(ei, ea);

    k_proj1<<<(NN + 7) / 8, 128>>>(x, W1l, W1r);
    k_agg1<<<(NN + 7) / 8, 256>>>(att1, W1e, b1, ln1g, ln1b);

    k_proj2<<<(NN + 31) / 32, 256>>>(W2l, W2r);
    k_agg2<<<(NN + 7) / 8, 256>>>(att2, W2e, b2, ln2g, ln2b, out);
}